// round 13
// baseline (speedup 1.0000x reference)
#include <cuda_runtime.h>
#include <cuda_bf16.h>

// GriddingDistance forward: trilinear scatter of two point clouds into two
// B x R x R x R fp32 grids (concatenated in d_out: pred first, gt second).
//
// R13 = R7 (best measured: 8x32MB chunks, serial scatters on origin stream,
// ONE side stream for memsets with AHEAD=2 throttle, R6 v4-window REDG body)
// with the pipeline FILL optimized: chunk 0 is zeroed by an SM store kernel
// on the main stream (~3us, L2-dirty lines handed straight to scatter 0)
// instead of an 8us copy-engine memset. Side stream zeroes chunks 1..7.

#ifndef GRID_B
#define GRID_B 16
#endif

#define NCHUNK 8                       // 4 per cloud, 4 batches (32MB) each
#define BPC    (2 * GRID_B / NCHUNK)   // batches per chunk = 4
#define AHEAD  2                       // memset k waits scatter[k-AHEAD]

__device__ __forceinline__ void red_add_v4(float* p, float a, float b, float c, float d) {
    asm volatile("red.global.add.v4.f32 [%0], {%1, %2, %3, %4};"
                 :: "l"(p), "f"(a), "f"(b), "f"(c), "f"(d) : "memory");
}
__device__ __forceinline__ void red_add_v2(float* p, float a, float b) {
    asm volatile("red.global.add.v2.f32 [%0], {%1, %2};"
                 :: "l"(p), "f"(a), "f"(b) : "memory");
}

// One xy-corner: add (w0, w1) at cells [idx, idx+1] via one v4 in the 16B
// window (pos<3), else v4 tail + scalar.
__device__ __forceinline__ void corner_pair(float* rowBase, long long idx,
                                            int pos, float w0, float w1)
{
    float* w = rowBase + (idx & ~3LL);
    if (pos == 0)      red_add_v4(w, w0, w1, 0.f, 0.f);
    else if (pos == 1) red_add_v4(w, 0.f, w0, w1, 0.f);
    else if (pos == 2) red_add_v4(w, 0.f, 0.f, w0, w1);
    else {
        red_add_v4(w, 0.f, 0.f, 0.f, w0);
        atomicAdd(rowBase + idx + 1, w1);
    }
}

__device__ __forceinline__ void scatter_point(
    float cx, float cy, float cz,
    float* __restrict__ dstBase,   // batch-region base
    int R, float Rf, float invR, bool rMod4)
{
    float vx = (cx * invR + 0.5f) * Rf;
    float vy = (cy * invR + 0.5f) * Rf;
    float vz = (cz * invR + 0.5f) * Rf;

    float flx = floorf(vx), fly = floorf(vy), flz = floorf(vz);
    int ix = (int)flx, iy = (int)fly, iz = (int)flz;
    float fx = vx - flx, fy = vy - fly, fz = vz - flz;

    float wx0 = 1.0f - fx, wx1 = fx;
    float wy0 = 1.0f - fy, wy1 = fy;
    float wz0 = 1.0f - fz, wz1 = fz;

    long long sY = R;
    long long sX = (long long)R * R;

    if (ix >= 0 && iy >= 0 && iz >= 0 && ix + 1 < R && iy + 1 < R && iz + 1 < R) {
        long long i000 = ((long long)ix * R + iy) * R + iz;
        if (rMod4) {
            int pos = (int)(i000 & 3LL);
            corner_pair(dstBase, i000,           pos, wx0 * wy0 * wz0, wx0 * wy0 * wz1);
            corner_pair(dstBase, i000 + sY,      pos, wx0 * wy1 * wz0, wx0 * wy1 * wz1);
            corner_pair(dstBase, i000 + sX,      pos, wx1 * wy0 * wz0, wx1 * wy0 * wz1);
            corner_pair(dstBase, i000 + sX + sY, pos, wx1 * wy1 * wz0, wx1 * wy1 * wz1);
        } else if ((i000 & 1LL) == 0) {
            float* g = dstBase + i000;
            red_add_v2(g,           wx0 * wy0 * wz0, wx0 * wy0 * wz1);
            red_add_v2(g + sY,      wx0 * wy1 * wz0, wx0 * wy1 * wz1);
            red_add_v2(g + sX,      wx1 * wy0 * wz0, wx1 * wy0 * wz1);
            red_add_v2(g + sX + sY, wx1 * wy1 * wz0, wx1 * wy1 * wz1);
        } else {
            float* g = dstBase + i000;
            atomicAdd(g,               wx0 * wy0 * wz0);
            atomicAdd(g + 1,           wx0 * wy0 * wz1);
            atomicAdd(g + sY,          wx0 * wy1 * wz0);
            atomicAdd(g + sY + 1,      wx0 * wy1 * wz1);
            atomicAdd(g + sX,          wx1 * wy0 * wz0);
            atomicAdd(g + sX + 1,      wx1 * wy0 * wz1);
            atomicAdd(g + sX + sY,     wx1 * wy1 * wz0);
            atomicAdd(g + sX + sY + 1, wx1 * wy1 * wz1);
        }
    } else {
        // Boundary path (reference: invalid corner contributes 0 -> skip)
        float wxa[2] = {wx0, wx1};
        float wya[2] = {wy0, wy1};
        float wza[2] = {wz0, wz1};
        #pragma unroll
        for (int dx = 0; dx < 2; dx++) {
            int x = ix + dx;
            if (x < 0 || x >= R) continue;
            #pragma unroll
            for (int dy = 0; dy < 2; dy++) {
                int y = iy + dy;
                if (y < 0 || y >= R) continue;
                #pragma unroll
                for (int dz = 0; dz < 2; dz++) {
                    int z = iz + dz;
                    if (z < 0 || z >= R) continue;
                    atomicAdd(dstBase + ((long long)x * R + y) * R + z,
                              wxa[dx] * wya[dy] * wza[dz]);
                }
            }
        }
    }
}

// SM zero-fill (for the pipeline-fill chunk): grid-stride float4 stores.
__global__ void __launch_bounds__(256)
zero_kernel(float4* __restrict__ dst, long long n4)
{
    long long stride = (long long)gridDim.x * blockDim.x;
    float4 z = make_float4(0.f, 0.f, 0.f, 0.f);
    for (long long q = blockIdx.x * blockDim.x + threadIdx.x; q < n4; q += stride)
        dst[q] = z;
}

// One chunk = BPC consecutive batches of one cloud. 2 points/thread.
__global__ void __launch_bounds__(256)
gridding_scatter2_kernel(
    const float* __restrict__ cloud,
    float* __restrict__ dst,
    int nPts, int npb,
    int R, float Rf, float invR,
    long long R3)
{
    int t = blockIdx.x * blockDim.x + threadIdx.x;
    int p0 = t * 2;
    if (p0 >= nPts) return;
    bool rMod4 = ((R & 3) == 0);

    if (p0 + 2 <= nPts) {
        const float2* c2 = (const float2*)cloud;   // 8B aligned: t*24 bytes
        float2 a = c2[3 * t + 0];
        float2 b = c2[3 * t + 1];
        float2 c = c2[3 * t + 2];
        {
            long long base = (long long)(p0 / npb) * R3;
            scatter_point(a.x, a.y, b.x, dst + base, R, Rf, invR, rMod4);
        }
        {
            long long base = (long long)((p0 + 1) / npb) * R3;
            scatter_point(b.y, c.x, c.y, dst + base, R, Rf, invR, rMod4);
        }
    } else {
        int p = p0;
        long long base = (long long)(p / npb) * R3;
        scatter_point(cloud[3 * p + 0], cloud[3 * p + 1], cloud[3 * p + 2],
                      dst + base, R, Rf, invR, rMod4);
    }
}

static inline int icbrt(long long v) {
    int r = (int)llroundf(cbrtf((float)v));
    while ((long long)(r + 1) * (r + 1) * (r + 1) <= v) r++;
    while ((long long)r * r * r > v) r--;
    return r;
}

// ONE side stream + events (rule-clean pattern), created on the first
// (uncaptured) correctness call; reused verbatim under graph capture.
struct OverlapCtx {
    cudaStream_t s1;
    cudaEvent_t  evFork;
    cudaEvent_t  evZero[NCHUNK];   // zero k done (k >= 1 on side stream)
    cudaEvent_t  evScat[NCHUNK];   // scatter k done
    OverlapCtx() {
        cudaStreamCreateWithFlags(&s1, cudaStreamNonBlocking);
        cudaEventCreateWithFlags(&evFork, cudaEventDisableTiming);
        for (int i = 0; i < NCHUNK; i++) {
            cudaEventCreateWithFlags(&evZero[i], cudaEventDisableTiming);
            cudaEventCreateWithFlags(&evScat[i], cudaEventDisableTiming);
        }
    }
};

extern "C" void kernel_launch(void* const* d_in, const int* in_sizes, int n_in,
                              void* d_out, int out_size)
{
    static OverlapCtx ctx;

    const float* pred = (const float*)d_in[0];
    const float* gt   = (const float*)d_in[1];
    float* out = (float*)d_out;

    int nPred = in_sizes[0] / 3;
    int nGt   = in_sizes[1] / 3;
    int B = GRID_B;
    long long cellsPerCloud = (long long)out_size / 2;   // B * R^3
    long long R3 = cellsPerCloud / B;                    // R^3
    int R = icbrt(R3);
    float Rf = (float)R;
    float invR = 1.0f / Rf;

    int npbPred = nPred / B;
    int npbGt   = nGt / B;

    long long chunkFloats = (long long)BPC * R3;
    const int chunksPerCloud = NCHUNK / 2;
    const int threads = 256;

    // Fork the side stream off the capture origin.
    cudaEventRecord(ctx.evFork, 0);
    cudaStreamWaitEvent(ctx.s1, ctx.evFork, 0);

    // Fill: zero chunk 0 with an SM kernel on the MAIN stream (fast, no
    // event edge; lines land dirty in L2 just before scatter 0 reads them).
    zero_kernel<<<512, threads>>>((float4*)out, chunkFloats >> 2);

    for (int k = 0; k < NCHUNK; k++) {
        // --- side stream: memset k (chunks 1..7 only), AHEAD-throttled ---
        if (k >= 1) {
            if (k >= AHEAD)
                cudaStreamWaitEvent(ctx.s1, ctx.evScat[k - AHEAD], 0);
            cudaMemsetAsync(out + (long long)k * chunkFloats, 0,
                            (size_t)chunkFloats * sizeof(float), ctx.s1);
            cudaEventRecord(ctx.evZero[k], ctx.s1);
            // --- main stream: scatter k gated on its memset ---
            cudaStreamWaitEvent(0, ctx.evZero[k], 0);
        }
        // (k == 0: scatter follows zero_kernel on the same stream.)

        bool isPred = (k < chunksPerCloud);
        const float* srcCloud = isPred ? pred : gt;
        int npb = isPred ? npbPred : npbGt;
        int ck = isPred ? k : (k - chunksPerCloud);
        int nPts = BPC * npb;

        const float* src = srcCloud + (long long)ck * BPC * npb * 3;
        float* dst = out + (long long)k * chunkFloats;

        int nThr = (nPts + 1) / 2;
        int blocks = (nThr + threads - 1) / threads;
        gridding_scatter2_kernel<<<blocks, threads>>>(
            src, dst, nPts, npb, R, Rf, invR, R3);
        cudaEventRecord(ctx.evScat[k], 0);
    }
    // Main stream's last scatter waited on evZero[NCHUNK-1]; side stream's
    // last memset precedes it -> side stream is rejoined.
}

// round 14
// speedup vs baseline: 1.1422x; 1.1422x over previous
#include <cuda_runtime.h>
#include <cuda_bf16.h>

// GriddingDistance forward: trilinear scatter of two point clouds into two
// B x R x R x R fp32 grids (concatenated in d_out: pred first, gt second).
//
// FINAL (= R7, best measured at 96.8us): 8 chunks of 32MB (4 batches each).
// ONE side stream zeroes chunk k; scatter k (main stream) waits on its
// memset. Memset k additionally waits on scatter k-2, so at most ~2 zeroed
// chunks (64MB < L2) are in flight: zeros stay L2-resident until their
// scatter consumes them -> atomics hit L2, zero-fill never round-trips DRAM.
// Scatter body: v4-window vector reductions (red.global.add.v4/v2), measured
// at the chip-shared L2 sector-RMW wall — invariant to further op/lane/
// concurrency changes (verified across R8-R13 perturbations).

#ifndef GRID_B
#define GRID_B 16
#endif

#define NCHUNK 8                       // 4 per cloud, 4 batches (32MB) each
#define BPC    (2 * GRID_B / NCHUNK)   // batches per chunk = 4
#define AHEAD  2                       // memset k waits scatter[k-AHEAD]

__device__ __forceinline__ void red_add_v4(float* p, float a, float b, float c, float d) {
    asm volatile("red.global.add.v4.f32 [%0], {%1, %2, %3, %4};"
                 :: "l"(p), "f"(a), "f"(b), "f"(c), "f"(d) : "memory");
}
__device__ __forceinline__ void red_add_v2(float* p, float a, float b) {
    asm volatile("red.global.add.v2.f32 [%0], {%1, %2};"
                 :: "l"(p), "f"(a), "f"(b) : "memory");
}

// One xy-corner: add (w0, w1) at cells [idx, idx+1] via one v4 in the 16B
// window (pos<3), else v4 tail + scalar.
__device__ __forceinline__ void corner_pair(float* rowBase, long long idx,
                                            int pos, float w0, float w1)
{
    float* w = rowBase + (idx & ~3LL);
    if (pos == 0)      red_add_v4(w, w0, w1, 0.f, 0.f);
    else if (pos == 1) red_add_v4(w, 0.f, w0, w1, 0.f);
    else if (pos == 2) red_add_v4(w, 0.f, 0.f, w0, w1);
    else {
        red_add_v4(w, 0.f, 0.f, 0.f, w0);
        atomicAdd(rowBase + idx + 1, w1);
    }
}

__device__ __forceinline__ void scatter_point(
    float cx, float cy, float cz,
    float* __restrict__ dstBase,   // batch-region base
    int R, float Rf, float invR, bool rMod4)
{
    float vx = (cx * invR + 0.5f) * Rf;
    float vy = (cy * invR + 0.5f) * Rf;
    float vz = (cz * invR + 0.5f) * Rf;

    float flx = floorf(vx), fly = floorf(vy), flz = floorf(vz);
    int ix = (int)flx, iy = (int)fly, iz = (int)flz;
    float fx = vx - flx, fy = vy - fly, fz = vz - flz;

    float wx0 = 1.0f - fx, wx1 = fx;
    float wy0 = 1.0f - fy, wy1 = fy;
    float wz0 = 1.0f - fz, wz1 = fz;

    long long sY = R;
    long long sX = (long long)R * R;

    if (ix >= 0 && iy >= 0 && iz >= 0 && ix + 1 < R && iy + 1 < R && iz + 1 < R) {
        long long i000 = ((long long)ix * R + iy) * R + iz;
        if (rMod4) {
            // R % 4 == 0: i000 & 3 == iz & 3, aligned window stays in-row.
            int pos = (int)(i000 & 3LL);
            corner_pair(dstBase, i000,           pos, wx0 * wy0 * wz0, wx0 * wy0 * wz1);
            corner_pair(dstBase, i000 + sY,      pos, wx0 * wy1 * wz0, wx0 * wy1 * wz1);
            corner_pair(dstBase, i000 + sX,      pos, wx1 * wy0 * wz0, wx1 * wy0 * wz1);
            corner_pair(dstBase, i000 + sX + sY, pos, wx1 * wy1 * wz0, wx1 * wy1 * wz1);
        } else if ((i000 & 1LL) == 0) {
            float* g = dstBase + i000;
            red_add_v2(g,           wx0 * wy0 * wz0, wx0 * wy0 * wz1);
            red_add_v2(g + sY,      wx0 * wy1 * wz0, wx0 * wy1 * wz1);
            red_add_v2(g + sX,      wx1 * wy0 * wz0, wx1 * wy0 * wz1);
            red_add_v2(g + sX + sY, wx1 * wy1 * wz0, wx1 * wy1 * wz1);
        } else {
            float* g = dstBase + i000;
            atomicAdd(g,               wx0 * wy0 * wz0);
            atomicAdd(g + 1,           wx0 * wy0 * wz1);
            atomicAdd(g + sY,          wx0 * wy1 * wz0);
            atomicAdd(g + sY + 1,      wx0 * wy1 * wz1);
            atomicAdd(g + sX,          wx1 * wy0 * wz0);
            atomicAdd(g + sX + 1,      wx1 * wy0 * wz1);
            atomicAdd(g + sX + sY,     wx1 * wy1 * wz0);
            atomicAdd(g + sX + sY + 1, wx1 * wy1 * wz1);
        }
    } else {
        // Boundary path (reference: invalid corner contributes 0 -> skip)
        float wxa[2] = {wx0, wx1};
        float wya[2] = {wy0, wy1};
        float wza[2] = {wz0, wz1};
        #pragma unroll
        for (int dx = 0; dx < 2; dx++) {
            int x = ix + dx;
            if (x < 0 || x >= R) continue;
            #pragma unroll
            for (int dy = 0; dy < 2; dy++) {
                int y = iy + dy;
                if (y < 0 || y >= R) continue;
                #pragma unroll
                for (int dz = 0; dz < 2; dz++) {
                    int z = iz + dz;
                    if (z < 0 || z >= R) continue;
                    atomicAdd(dstBase + ((long long)x * R + y) * R + z,
                              wxa[dx] * wya[dy] * wza[dz]);
                }
            }
        }
    }
}

// One chunk = BPC consecutive batches of one cloud. 2 points/thread.
__global__ void __launch_bounds__(256)
gridding_scatter2_kernel(
    const float* __restrict__ cloud,
    float* __restrict__ dst,
    int nPts, int npb,
    int R, float Rf, float invR,
    long long R3)
{
    int t = blockIdx.x * blockDim.x + threadIdx.x;
    int p0 = t * 2;
    if (p0 >= nPts) return;
    bool rMod4 = ((R & 3) == 0);

    if (p0 + 2 <= nPts) {
        const float2* c2 = (const float2*)cloud;   // 8B aligned: t*24 bytes
        float2 a = c2[3 * t + 0];
        float2 b = c2[3 * t + 1];
        float2 c = c2[3 * t + 2];
        {
            long long base = (long long)(p0 / npb) * R3;
            scatter_point(a.x, a.y, b.x, dst + base, R, Rf, invR, rMod4);
        }
        {
            long long base = (long long)((p0 + 1) / npb) * R3;
            scatter_point(b.y, c.x, c.y, dst + base, R, Rf, invR, rMod4);
        }
    } else {
        int p = p0;
        long long base = (long long)(p / npb) * R3;
        scatter_point(cloud[3 * p + 0], cloud[3 * p + 1], cloud[3 * p + 2],
                      dst + base, R, Rf, invR, rMod4);
    }
}

static inline int icbrt(long long v) {
    int r = (int)llroundf(cbrtf((float)v));
    while ((long long)(r + 1) * (r + 1) * (r + 1) <= v) r++;
    while ((long long)r * r * r > v) r--;
    return r;
}

// ONE side stream + events (rule-clean pattern), created on the first
// (uncaptured) correctness call; reused verbatim under graph capture.
struct OverlapCtx {
    cudaStream_t s1;
    cudaEvent_t  evFork;
    cudaEvent_t  evZero[NCHUNK];   // memset k done
    cudaEvent_t  evScat[NCHUNK];   // scatter k done
    OverlapCtx() {
        cudaStreamCreateWithFlags(&s1, cudaStreamNonBlocking);
        cudaEventCreateWithFlags(&evFork, cudaEventDisableTiming);
        for (int i = 0; i < NCHUNK; i++) {
            cudaEventCreateWithFlags(&evZero[i], cudaEventDisableTiming);
            cudaEventCreateWithFlags(&evScat[i], cudaEventDisableTiming);
        }
    }
};

extern "C" void kernel_launch(void* const* d_in, const int* in_sizes, int n_in,
                              void* d_out, int out_size)
{
    static OverlapCtx ctx;

    const float* pred = (const float*)d_in[0];
    const float* gt   = (const float*)d_in[1];
    float* out = (float*)d_out;

    int nPred = in_sizes[0] / 3;
    int nGt   = in_sizes[1] / 3;
    int B = GRID_B;
    long long cellsPerCloud = (long long)out_size / 2;   // B * R^3
    long long R3 = cellsPerCloud / B;                    // R^3
    int R = icbrt(R3);
    float Rf = (float)R;
    float invR = 1.0f / Rf;

    int npbPred = nPred / B;
    int npbGt   = nGt / B;

    long long chunkFloats = (long long)BPC * R3;
    const int chunksPerCloud = NCHUNK / 2;
    const int threads = 256;

    // Fork the side stream off the capture origin.
    cudaEventRecord(ctx.evFork, 0);
    cudaStreamWaitEvent(ctx.s1, ctx.evFork, 0);

    // Interleave: side stream zeroes chunk k (throttled to stay <= AHEAD
    // chunks ahead of the scatters); main stream scatters chunk k after its
    // memset. Record order keeps each event recorded before it is waited on.
    for (int k = 0; k < NCHUNK; k++) {
        // --- side stream: memset k ---
        if (k >= AHEAD)
            cudaStreamWaitEvent(ctx.s1, ctx.evScat[k - AHEAD], 0);
        cudaMemsetAsync(out + (long long)k * chunkFloats, 0,
                        (size_t)chunkFloats * sizeof(float), ctx.s1);
        cudaEventRecord(ctx.evZero[k], ctx.s1);

        // --- main stream: scatter k ---
        cudaStreamWaitEvent(0, ctx.evZero[k], 0);

        bool isPred = (k < chunksPerCloud);
        const float* srcCloud = isPred ? pred : gt;
        int npb = isPred ? npbPred : npbGt;
        int ck = isPred ? k : (k - chunksPerCloud);
        int nPts = BPC * npb;

        const float* src = srcCloud + (long long)ck * BPC * npb * 3;
        float* dst = out + (long long)k * chunkFloats;

        int nThr = (nPts + 1) / 2;
        int blocks = (nThr + threads - 1) / threads;
        gridding_scatter2_kernel<<<blocks, threads>>>(
            src, dst, nPts, npb, R, Rf, invR, R3);
        cudaEventRecord(ctx.evScat[k], 0);
    }
    // Main stream's last op waited on evZero[NCHUNK-1]; side stream's last
    // memset precedes it -> side stream is rejoined at the final scatter.
}